// round 5
// baseline (speedup 1.0000x reference)
#include <cuda_runtime.h>
#include <cstdint>

#define NNODES 50000
#define MAXE   800000
#define OUTD   128

// ---------------- device scratch (no allocations allowed) ----------------
__device__ int   g_cnt[NNODES];        // per-node edge count
__device__ int   g_start[NNODES + 1];  // CSR row offsets (exclusive scan)
__device__ int   g_cursor[NNODES];     // bucket-fill cursors
__device__ int   g_edges[MAXE];        // edge ids grouped by destination node
__device__ float g_WcT[OUTD * OUTD];   // (W2@W1) transposed: [k][o]
__device__ float g_bc[OUTD];           // W2 @ b1

// ---------------- f32x2 packed-FMA helpers ----------------
__device__ __forceinline__ unsigned long long pack2(float x, float y) {
    unsigned long long r;
    asm("mov.b64 %0, {%1, %2};" : "=l"(r) : "f"(x), "f"(y));
    return r;
}
__device__ __forceinline__ void unpack2(unsigned long long v, float& x, float& y) {
    asm("mov.b64 {%0, %1}, %2;" : "=f"(x), "=f"(y) : "l"(v));
}
__device__ __forceinline__ void ffma2(unsigned long long& d,
                                      unsigned long long a,
                                      unsigned long long b) {
    asm("fma.rn.f32x2 %0, %1, %2, %0;" : "+l"(d) : "l"(a), "l"(b));
}

// ---------------- prep: Wc = W2 @ W1 (store transposed), bc = W2 @ b1 ----
__global__ void wct_kernel(const float* __restrict__ W1,   // [512, 128]
                           const float* __restrict__ W2) { // [128, 512]
    int o = blockIdx.x;
    int k = threadIdx.x;
    const float* w2row = W2 + (size_t)o * 512;
    float acc = 0.f;
    #pragma unroll 8
    for (int h = 0; h < 512; ++h)
        acc += w2row[h] * W1[(size_t)h * OUTD + k];
    g_WcT[k * OUTD + o] = acc;
}

__global__ void bc_kernel(const float* __restrict__ W2, const float* __restrict__ b1) {
    int o = threadIdx.x;
    float acc = 0.f;
    #pragma unroll 8
    for (int h = 0; h < 512; ++h)
        acc += W2[(size_t)o * 512 + h] * b1[h];
    g_bc[o] = acc;
}

// ---------------- CSR build --------------------------------------------
__global__ void zero_cnt_kernel() {
    int i = blockIdx.x * blockDim.x + threadIdx.x;
    if (i < NNODES) g_cnt[i] = 0;
}

__global__ void hist_kernel(const int* __restrict__ index, int E) {
    int i = blockIdx.x * blockDim.x + threadIdx.x;
    if (i < E) atomicAdd(&g_cnt[__ldg(index + i)], 1);
}

// single-block exclusive scan of 50000 counters -> g_start, g_cursor
__global__ void __launch_bounds__(1024) scan_kernel() {
    __shared__ int part[1024];
    const int t = threadIdx.x;
    const int CH = (NNODES + 1023) / 1024;            // 49
    int lo = t * CH, hi = min(lo + CH, NNODES);
    int s = 0;
    for (int i = lo; i < hi; ++i) s += g_cnt[i];
    part[t] = s;
    __syncthreads();
    for (int d = 1; d < 1024; d <<= 1) {
        int v = (t >= d) ? part[t - d] : 0;
        __syncthreads();
        part[t] += v;
        __syncthreads();
    }
    int run = (t > 0) ? part[t - 1] : 0;              // exclusive base
    for (int i = lo; i < hi; ++i) {
        int c = g_cnt[i];
        g_start[i]  = run;
        g_cursor[i] = run;
        run += c;
    }
    if (t == 1023) g_start[NNODES] = run;
}

__global__ void bucket_kernel(const int* __restrict__ index, int E) {
    int i = blockIdx.x * blockDim.x + threadIdx.x;
    if (i < E) {
        int n = __ldg(index + i);
        int pos = atomicAdd(&g_cursor[n], 1);
        g_edges[pos] = i;
    }
}

// ---------------- fused gather + GEMM + epilogue -------------------------
// 64 nodes/block, 256 threads, 48KB STATIC smem (no attribute call needed).
// Phase 1: 8 warps gather-sum edge rows into sST[k][r] (transposed, XOR-swizzled).
// Phase 2: 4 column passes; WcT chunk [128][32] staged per pass; f32x2 FMAs.
// Element (k, r) lives at sST[k*64 + (r ^ (k & 63))]  -> conflict-free GEMM reads.
__global__ void __launch_bounds__(256) fused_kernel(const float4* __restrict__ msg4,
                                                    const float* __restrict__ b2,
                                                    float* __restrict__ out, int N) {
    __shared__ float sW[128 * 32];     // 16 KB: WcT column chunk [k][32]
    __shared__ float sST[128 * 64];    // 32 KB: gathered S, transposed+swizzled

    const int t    = threadIdx.x;
    const int lane = t & 31;
    const int w    = t >> 5;
    const int row0 = blockIdx.x * 64;

    // ---- gather: warp w handles nodes row0 + w*8 .. +7 ----
    #pragma unroll 1
    for (int j = 0; j < 8; ++j) {
        int r = w * 8 + j;
        int n = row0 + r;
        float4 a0 = make_float4(0.f, 0.f, 0.f, 0.f);
        float4 a1 = make_float4(0.f, 0.f, 0.f, 0.f);
        float4 a2 = make_float4(0.f, 0.f, 0.f, 0.f);
        float4 a3 = make_float4(0.f, 0.f, 0.f, 0.f);
        if (n < N) {
            int s0 = __ldg(&g_start[n]);
            int s1 = __ldg(&g_start[n + 1]);
            for (int base = s0; base < s1; base += 32) {
                int m = min(32, s1 - base);
                int eid = 0;
                if (base + lane < s1) eid = __ldg(&g_edges[base + lane]);
                int i = 0;
                for (; i + 3 < m; i += 4) {
                    int e0 = __shfl_sync(0xffffffffu, eid, i);
                    int e1 = __shfl_sync(0xffffffffu, eid, i + 1);
                    int e2 = __shfl_sync(0xffffffffu, eid, i + 2);
                    int e3 = __shfl_sync(0xffffffffu, eid, i + 3);
                    float4 v0 = __ldg(msg4 + (size_t)e0 * 32 + lane);
                    float4 v1 = __ldg(msg4 + (size_t)e1 * 32 + lane);
                    float4 v2 = __ldg(msg4 + (size_t)e2 * 32 + lane);
                    float4 v3 = __ldg(msg4 + (size_t)e3 * 32 + lane);
                    a0.x += v0.x; a0.y += v0.y; a0.z += v0.z; a0.w += v0.w;
                    a1.x += v1.x; a1.y += v1.y; a1.z += v1.z; a1.w += v1.w;
                    a2.x += v2.x; a2.y += v2.y; a2.z += v2.z; a2.w += v2.w;
                    a3.x += v3.x; a3.y += v3.y; a3.z += v3.z; a3.w += v3.w;
                }
                for (; i < m; ++i) {
                    int e0 = __shfl_sync(0xffffffffu, eid, i);
                    float4 v0 = __ldg(msg4 + (size_t)e0 * 32 + lane);
                    a0.x += v0.x; a0.y += v0.y; a0.z += v0.z; a0.w += v0.w;
                }
            }
        }
        a0.x += a1.x + a2.x + a3.x;
        a0.y += a1.y + a2.y + a3.y;
        a0.z += a1.z + a2.z + a3.z;
        a0.w += a1.w + a2.w + a3.w;
        // scatter 4 scalars into transposed swizzled layout (k = 4*lane + q)
        int k0 = 4 * lane;
        sST[(k0 + 0) * 64 + (r ^ ((k0 + 0) & 63))] = a0.x;
        sST[(k0 + 1) * 64 + (r ^ ((k0 + 1) & 63))] = a0.y;
        sST[(k0 + 2) * 64 + (r ^ ((k0 + 2) & 63))] = a0.z;
        sST[(k0 + 3) * 64 + (r ^ ((k0 + 3) & 63))] = a0.w;
    }

    // ---- GEMM: 4 column passes of 32 ----
    const int tx = t & 7;              // col group: 4 cols
    const int ty = t >> 3;             // row group: 2 rows
    const int rA = 2 * ty;
    const int rB = 2 * ty + 1;
    const int nA = row0 + rA;
    const int nB = row0 + rB;
    float cntA = 0.f, cntB = 0.f;
    if (nA < N) cntA = (float)(__ldg(&g_start[nA + 1]) - __ldg(&g_start[nA]));
    if (nB < N) cntB = (float)(__ldg(&g_start[nB + 1]) - __ldg(&g_start[nB]));

    #pragma unroll 1
    for (int p = 0; p < 4; ++p) {
        __syncthreads();               // gather done / previous pass reads done
        // stage WcT chunk [128][32]: sW4[k*8 + c4] = W4[k*32 + p*8 + c4]
        {
            float4* sW4 = (float4*)sW;
            const float4* W4 = (const float4*)g_WcT;
            #pragma unroll
            for (int i = 0; i < 4; ++i) {
                int f = t + 256 * i;
                int k = f >> 3, c4 = f & 7;
                sW4[f] = W4[k * 32 + p * 8 + c4];
            }
        }
        __syncthreads();

        unsigned long long accA0 = 0ull, accA1 = 0ull, accB0 = 0ull, accB1 = 0ull;
        #pragma unroll 4
        for (int k = 0; k < 128; ++k) {
            float4 wv = *(const float4*)(sW + k * 32 + tx * 4);
            unsigned long long w0 = pack2(wv.x, wv.y);
            unsigned long long w1 = pack2(wv.z, wv.w);
            float sA = sST[k * 64 + (rA ^ (k & 63))];
            float sB = sST[k * 64 + (rB ^ (k & 63))];
            unsigned long long ssA = pack2(sA, sA);
            unsigned long long ssB = pack2(sB, sB);
            ffma2(accA0, ssA, w0);
            ffma2(accA1, ssA, w1);
            ffma2(accB0, ssB, w0);
            ffma2(accB1, ssB, w1);
        }

        // epilogue for this column pass
        int c = p * 32 + tx * 4;
        float bc0 = g_bc[c],     bc1 = g_bc[c + 1];
        float bc2 = g_bc[c + 2], bc3 = g_bc[c + 3];
        float b20 = __ldg(b2 + c),     b21 = __ldg(b2 + c + 1);
        float b22 = __ldg(b2 + c + 2), b23 = __ldg(b2 + c + 3);
        if (nA < N) {
            float x0, x1, x2, x3;
            unpack2(accA0, x0, x1); unpack2(accA1, x2, x3);
            x0 += cntA * bc0 + b20; x1 += cntA * bc1 + b21;
            x2 += cntA * bc2 + b22; x3 += cntA * bc3 + b23;
            x0 = (x0 >= 0.f) ? x0 : 0.01f * x0;
            x1 = (x1 >= 0.f) ? x1 : 0.01f * x1;
            x2 = (x2 >= 0.f) ? x2 : 0.01f * x2;
            x3 = (x3 >= 0.f) ? x3 : 0.01f * x3;
            *(float4*)(out + (size_t)nA * OUTD + c) = make_float4(x0, x1, x2, x3);
        }
        if (nB < N) {
            float x0, x1, x2, x3;
            unpack2(accB0, x0, x1); unpack2(accB1, x2, x3);
            x0 += cntB * bc0 + b20; x1 += cntB * bc1 + b21;
            x2 += cntB * bc2 + b22; x3 += cntB * bc3 + b23;
            x0 = (x0 >= 0.f) ? x0 : 0.01f * x0;
            x1 = (x1 >= 0.f) ? x1 : 0.01f * x1;
            x2 = (x2 >= 0.f) ? x2 : 0.01f * x2;
            x3 = (x3 >= 0.f) ? x3 : 0.01f * x3;
            *(float4*)(out + (size_t)nB * OUTD + c) = make_float4(x0, x1, x2, x3);
        }
    }
}

// ---------------- launch: pure kernel launches, nothing else -------------
extern "C" void kernel_launch(void* const* d_in, const int* in_sizes, int n_in,
                              void* d_out, int out_size) {
    // metadata order: msg, x_i, x_j, e_ij, index, num_nodes, W1, b1, W2, b2
    const float* msg   = (const float*)d_in[0];
    const int*   index = (const int*)  d_in[4];
    const float* W1    = (const float*)d_in[6];
    const float* b1    = (const float*)d_in[7];
    const float* W2    = (const float*)d_in[8];
    const float* b2    = (const float*)d_in[9];
    float* out = (float*)d_out;

    int E = in_sizes[4];
    if (E > MAXE) E = MAXE;
    int N = out_size / OUTD;
    if (N > NNODES) N = NNODES;

    wct_kernel<<<OUTD, OUTD>>>(W1, W2);
    bc_kernel<<<1, OUTD>>>(W2, b1);
    zero_cnt_kernel<<<(NNODES + 255) / 256, 256>>>();
    hist_kernel<<<(E + 255) / 256, 256>>>(index, E);
    scan_kernel<<<1, 1024>>>();
    bucket_kernel<<<(E + 255) / 256, 256>>>(index, E);
    fused_kernel<<<(N + 63) / 64, 256>>>((const float4*)msg, b2, out, N);
}

// round 6
// speedup vs baseline: 1.2815x; 1.2815x over previous
#include <cuda_runtime.h>
#include <cstdint>

#define NNODES 50000
#define OUTD   128

// ---------------- device scratch (no allocations allowed) ----------------
__device__ float4 g_S4[NNODES * (OUTD / 4)];   // 25.6 MB accumulator S[N][128]
__device__ float  g_cnt[NNODES];               // per-node edge count (as float)
__device__ float  g_WcT[OUTD * OUTD];          // (W2@W1) transposed: [k][o]
__device__ float  g_bc[OUTD];                  // W2 @ b1

// ---------------- f32x2 packed-FMA helpers ----------------
__device__ __forceinline__ unsigned long long pack2(float x, float y) {
    unsigned long long r;
    asm("mov.b64 %0, {%1, %2};" : "=l"(r) : "f"(x), "f"(y));
    return r;
}
__device__ __forceinline__ void unpack2(unsigned long long v, float& x, float& y) {
    asm("mov.b64 {%0, %1}, %2;" : "=f"(x), "=f"(y) : "l"(v));
}
__device__ __forceinline__ void ffma2(unsigned long long& d,
                                      unsigned long long a,
                                      unsigned long long b) {
    asm("fma.rn.f32x2 %0, %1, %2, %0;" : "+l"(d) : "l"(a), "l"(b));
}
__device__ __forceinline__ void red4(float* dst, float4 v) {
    asm volatile("red.global.add.v4.f32 [%0], {%1, %2, %3, %4};"
                 :: "l"(dst), "f"(v.x), "f"(v.y), "f"(v.z), "f"(v.w)
                 : "memory");
}

// ---------------- prep: Wc = W2 @ W1 (store transposed), bc = W2 @ b1 ----
__global__ void wct_kernel(const float* __restrict__ W1,   // [512, 128]
                           const float* __restrict__ W2) { // [128, 512]
    int o = blockIdx.x;
    int k = threadIdx.x;
    const float* w2row = W2 + (size_t)o * 512;
    float acc = 0.f;
    #pragma unroll 8
    for (int h = 0; h < 512; ++h)
        acc += w2row[h] * W1[(size_t)h * OUTD + k];
    g_WcT[k * OUTD + o] = acc;
}

__global__ void bc_kernel(const float* __restrict__ W2, const float* __restrict__ b1) {
    int o = threadIdx.x;
    float acc = 0.f;
    #pragma unroll 8
    for (int h = 0; h < 512; ++h)
        acc += W2[(size_t)o * 512 + h] * b1[h];
    g_bc[o] = acc;
}

// ---------------- zero the accumulators (every replay) -------------------
__global__ void zero_kernel() {
    int i = blockIdx.x * blockDim.x + threadIdx.x;
    int stride = gridDim.x * blockDim.x;
    const int n4 = NNODES * (OUTD / 4);
    for (int j = i; j < n4; j += stride) g_S4[j] = make_float4(0.f, 0.f, 0.f, 0.f);
    for (int j = i; j < NNODES; j += stride) g_cnt[j] = 0.f;
}

// ---------------- scatter: S[index[e]] += msg[e], cnt[index[e]] += 1 -----
// Warp per edge, 4 edges in flight per iteration (MLP=4 before first red).
__global__ void scatter_kernel(const float4* __restrict__ msg4,
                               const int* __restrict__ index, int E) {
    int lane  = threadIdx.x & 31;
    int warp  = (blockIdx.x * blockDim.x + threadIdx.x) >> 5;
    int nwarp = (gridDim.x * blockDim.x) >> 5;

    int e = warp;
    for (; e + 3 * nwarp < E; e += 4 * nwarp) {
        int e0 = e, e1 = e + nwarp, e2 = e + 2 * nwarp, e3 = e + 3 * nwarp;
        int n0 = __ldg(index + e0);
        int n1 = __ldg(index + e1);
        int n2 = __ldg(index + e2);
        int n3 = __ldg(index + e3);
        float4 v0 = __ldg(msg4 + (size_t)e0 * 32 + lane);
        float4 v1 = __ldg(msg4 + (size_t)e1 * 32 + lane);
        float4 v2 = __ldg(msg4 + (size_t)e2 * 32 + lane);
        float4 v3 = __ldg(msg4 + (size_t)e3 * 32 + lane);
        red4((float*)&g_S4[(size_t)n0 * 32 + lane], v0);
        red4((float*)&g_S4[(size_t)n1 * 32 + lane], v1);
        red4((float*)&g_S4[(size_t)n2 * 32 + lane], v2);
        red4((float*)&g_S4[(size_t)n3 * 32 + lane], v3);
        if (lane == 0) {
            atomicAdd(&g_cnt[n0], 1.0f);
            atomicAdd(&g_cnt[n1], 1.0f);
            atomicAdd(&g_cnt[n2], 1.0f);
            atomicAdd(&g_cnt[n3], 1.0f);
        }
    }
    for (; e < E; e += nwarp) {
        int n = __ldg(index + e);
        float4 v = __ldg(msg4 + (size_t)e * 32 + lane);
        red4((float*)&g_S4[(size_t)n * 32 + lane], v);
        if (lane == 0) atomicAdd(&g_cnt[n], 1.0f);
    }
}

// ---------------- final: out = leaky(S @ WcT + cnt*bc + b2) --------------
// 64 nodes/block, 256 threads, 48 KB static smem.
// S tile loaded coalesced (MLP=8) into transposed+XOR-swizzled sST[k][r];
// WcT staged in 4 column passes of 32; per-thread 2 rows x 4 cols, f32x2 FMAs.
// sST element (k, r) at sST[k*64 + (r ^ (k & 63))] -> conflict-free GEMM reads.
__global__ void __launch_bounds__(256) final_kernel(const float* __restrict__ b2,
                                                    float* __restrict__ out, int N) {
    __shared__ float sW[128 * 32];     // 16 KB: WcT column chunk [k][32]
    __shared__ float sST[128 * 64];    // 32 KB: S tile, transposed+swizzled

    const int t    = threadIdx.x;
    const int row0 = blockIdx.x * 64;

    // ---- load S tile: 8 independent coalesced float4 loads per thread ----
    {
        float4 v[8];
        #pragma unroll
        for (int j = 0; j < 8; ++j) {
            int f = t + 256 * j;
            int r = f >> 5;            // node row within tile (const per warp)
            int c4 = f & 31;           // float4 column
            int n = row0 + r;
            v[j] = make_float4(0.f, 0.f, 0.f, 0.f);
            if (n < N) v[j] = __ldg(&g_S4[(size_t)n * 32 + c4]);
        }
        #pragma unroll
        for (int j = 0; j < 8; ++j) {
            int f = t + 256 * j;
            int r = f >> 5;
            int k0 = (f & 31) * 4;
            sST[(k0 + 0) * 64 + (r ^ ((k0 + 0) & 63))] = v[j].x;
            sST[(k0 + 1) * 64 + (r ^ ((k0 + 1) & 63))] = v[j].y;
            sST[(k0 + 2) * 64 + (r ^ ((k0 + 2) & 63))] = v[j].z;
            sST[(k0 + 3) * 64 + (r ^ ((k0 + 3) & 63))] = v[j].w;
        }
    }

    // ---- GEMM: 4 column passes of 32 ----
    const int tx = t & 7;              // col group: 4 cols
    const int ty = t >> 3;             // row group: 2 rows
    const int rA = 2 * ty;
    const int rB = 2 * ty + 1;
    const int nA = row0 + rA;
    const int nB = row0 + rB;
    float cntA = (nA < N) ? g_cnt[nA] : 0.f;
    float cntB = (nB < N) ? g_cnt[nB] : 0.f;

    #pragma unroll 1
    for (int p = 0; p < 4; ++p) {
        __syncthreads();               // sST ready / previous pass reads done
        // stage WcT chunk [128][32]
        {
            float4* sW4 = (float4*)sW;
            const float4* W4 = (const float4*)g_WcT;
            #pragma unroll
            for (int i = 0; i < 4; ++i) {
                int f = t + 256 * i;
                int k = f >> 3, c4 = f & 7;
                sW4[f] = W4[k * 32 + p * 8 + c4];
            }
        }
        __syncthreads();

        unsigned long long accA0 = 0ull, accA1 = 0ull, accB0 = 0ull, accB1 = 0ull;
        #pragma unroll 4
        for (int k = 0; k < 128; ++k) {
            float4 wv = *(const float4*)(sW + k * 32 + tx * 4);
            unsigned long long w0 = pack2(wv.x, wv.y);
            unsigned long long w1 = pack2(wv.z, wv.w);
            float sA = sST[k * 64 + (rA ^ (k & 63))];
            float sB = sST[k * 64 + (rB ^ (k & 63))];
            unsigned long long ssA = pack2(sA, sA);
            unsigned long long ssB = pack2(sB, sB);
            ffma2(accA0, ssA, w0);
            ffma2(accA1, ssA, w1);
            ffma2(accB0, ssB, w0);
            ffma2(accB1, ssB, w1);
        }

        // epilogue for this column pass
        int c = p * 32 + tx * 4;
        float bc0 = g_bc[c],     bc1 = g_bc[c + 1];
        float bc2 = g_bc[c + 2], bc3 = g_bc[c + 3];
        float b20 = __ldg(b2 + c),     b21 = __ldg(b2 + c + 1);
        float b22 = __ldg(b2 + c + 2), b23 = __ldg(b2 + c + 3);
        if (nA < N) {
            float x0, x1, x2, x3;
            unpack2(accA0, x0, x1); unpack2(accA1, x2, x3);
            x0 += cntA * bc0 + b20; x1 += cntA * bc1 + b21;
            x2 += cntA * bc2 + b22; x3 += cntA * bc3 + b23;
            x0 = (x0 >= 0.f) ? x0 : 0.01f * x0;
            x1 = (x1 >= 0.f) ? x1 : 0.01f * x1;
            x2 = (x2 >= 0.f) ? x2 : 0.01f * x2;
            x3 = (x3 >= 0.f) ? x3 : 0.01f * x3;
            *(float4*)(out + (size_t)nA * OUTD + c) = make_float4(x0, x1, x2, x3);
        }
        if (nB < N) {
            float x0, x1, x2, x3;
            unpack2(accB0, x0, x1); unpack2(accB1, x2, x3);
            x0 += cntB * bc0 + b20; x1 += cntB * bc1 + b21;
            x2 += cntB * bc2 + b22; x3 += cntB * bc3 + b23;
            x0 = (x0 >= 0.f) ? x0 : 0.01f * x0;
            x1 = (x1 >= 0.f) ? x1 : 0.01f * x1;
            x2 = (x2 >= 0.f) ? x2 : 0.01f * x2;
            x3 = (x3 >= 0.f) ? x3 : 0.01f * x3;
            *(float4*)(out + (size_t)nB * OUTD + c) = make_float4(x0, x1, x2, x3);
        }
    }
}

// ---------------- launch: pure kernel launches ---------------------------
extern "C" void kernel_launch(void* const* d_in, const int* in_sizes, int n_in,
                              void* d_out, int out_size) {
    // metadata order: msg, x_i, x_j, e_ij, index, num_nodes, W1, b1, W2, b2
    const float* msg   = (const float*)d_in[0];
    const int*   index = (const int*)  d_in[4];
    const float* W1    = (const float*)d_in[6];
    const float* b1    = (const float*)d_in[7];
    const float* W2    = (const float*)d_in[8];
    const float* b2    = (const float*)d_in[9];
    float* out = (float*)d_out;

    int E = in_sizes[4];
    int N = out_size / OUTD;
    if (N > NNODES) N = NNODES;

    wct_kernel<<<OUTD, OUTD>>>(W1, W2);
    bc_kernel<<<1, OUTD>>>(W2, b1);
    zero_kernel<<<2048, 256>>>();
    scatter_kernel<<<12500, 256>>>((const float4*)msg, index, E);
    final_kernel<<<(N + 63) / 64, 256>>>(b2, out, N);
}